// round 9
// baseline (speedup 1.0000x reference)
#include <cuda_runtime.h>
#include <cuda_fp16.h>
#include <cstdint>
#include <math.h>

// ---------------- problem constants ----------------
#define NTOK   65536
#define CDIM   512
#define NWIN   512
#define LWIN   128
#define NHEAD  8
#define HDIM   64

// ---------------- scratch ----------------
__device__ __half g_x16[(size_t)NTOK * CDIM];   // windowed x, fp16
__device__ __half g_q16[(size_t)NTOK * CDIM];   // Q pre-scaled by 0.125
__device__ __half g_k16[(size_t)NTOK * CDIM];
__device__ __half g_v16[(size_t)NTOK * CDIM];
__device__ __half g_ao[(size_t)NTOK * CDIM];    // attention output (windowed rows)
__device__ __half g_w16[(size_t)4 * CDIM * CDIM];

// windowed row m -> natural token index n
__device__ __forceinline__ int win_to_src(int m) {
    int w = m >> 7, l = m & 127;
    int w1 = w & 7, h1 = (w >> 3) & 7, f1 = w >> 6;
    int iw = l & 7, ih = (l >> 3) & 7, t  = l >> 6;
    return ((f1 * 2 + t) << 12) + ((h1 * 8 + ih) << 6) + (w1 * 8 + iw);
}

// ---------------- PTX helpers ----------------
__device__ __forceinline__ uint32_t smem_u32(const void* p) {
    uint32_t a;
    asm("{ .reg .u64 t; cvta.to.shared.u64 t, %1; cvt.u32.u64 %0, t; }" : "=r"(a) : "l"(p));
    return a;
}
#define CP16(dst, src) \
    asm volatile("cp.async.cg.shared.global [%0], [%1], 16;" :: "r"(dst), "l"(src))
#define CP_COMMIT() asm volatile("cp.async.commit_group;" ::: "memory")
#define CP_WAIT1()  asm volatile("cp.async.wait_group 1;" ::: "memory")
#define CP_WAIT0()  asm volatile("cp.async.wait_group 0;" ::: "memory")

#define LDSM4(r0, r1, r2, r3, a) \
    asm volatile("ldmatrix.sync.aligned.m8n8.x4.shared.b16 {%0,%1,%2,%3}, [%4];" \
                 : "=r"(r0), "=r"(r1), "=r"(r2), "=r"(r3) : "r"(a))
#define LDSM4T(r0, r1, r2, r3, a) \
    asm volatile("ldmatrix.sync.aligned.m8n8.x4.trans.shared.b16 {%0,%1,%2,%3}, [%4];" \
                 : "=r"(r0), "=r"(r1), "=r"(r2), "=r"(r3) : "r"(a))

// c += a * {b0,b1}
#define MMA_F16P(c, a, b0, b1) \
    asm volatile("mma.sync.aligned.m16n8k16.row.col.f32.f16.f16.f32 " \
                 "{%0,%1,%2,%3}, {%4,%5,%6,%7}, {%8,%9}, {%0,%1,%2,%3};" \
                 : "+f"((c)[0]), "+f"((c)[1]), "+f"((c)[2]), "+f"((c)[3]) \
                 : "r"((a)[0]), "r"((a)[1]), "r"((a)[2]), "r"((a)[3]), \
                   "r"(b0), "r"(b1))
#define MMA_F16(c, a, b) MMA_F16P(c, a, (b)[0], (b)[1])

__device__ __forceinline__ uint32_t pkh(float a, float b) {
    __half2 h = __float22half2_rn(make_float2(a, b));
    return *reinterpret_cast<uint32_t*>(&h);
}

// =====================================================================
// conversion kernels
// =====================================================================
__global__ void convert_x(const float* __restrict__ x) {
    int idx = blockIdx.x * 256 + threadIdx.x;
    int m = idx >> 7, q = idx & 127;
    int n = win_to_src(m);
    float4 v = *(const float4*)(x + (size_t)n * CDIM + q * 4);
    __half* dst = g_x16 + (size_t)m * CDIM + q * 4;
    *(__half2*)(dst)     = __float22half2_rn(make_float2(v.x, v.y));
    *(__half2*)(dst + 2) = __float22half2_rn(make_float2(v.z, v.w));
}

__global__ void convert_w(const float* __restrict__ Wq, const float* __restrict__ Wk,
                          const float* __restrict__ Wv, const float* __restrict__ Wo) {
    int sel = blockIdx.x >> 8;
    int rem = (blockIdx.x & 255) * 256 + threadIdx.x;
    const float* W = (sel == 0) ? Wq : (sel == 1) ? Wk : (sel == 2) ? Wv : Wo;
    float4 v = *(const float4*)(W + (size_t)rem * 4);
    __half* dst = g_w16 + (size_t)sel * CDIM * CDIM + (size_t)rem * 4;
    *(__half2*)(dst)     = __float22half2_rn(make_float2(v.x, v.y));
    *(__half2*)(dst + 2) = __float22half2_rn(make_float2(v.z, v.w));
}

// =====================================================================
// GEMM v3: C[128,256] = A[128,512] @ B[256,512]^T, fp16 in, f32 acc.
// 256 threads = 8 warps (2m x 4n), warp tile 64x64 (CUTLASS shape).
// BK=64, 3-stage cp.async ring, one barrier per chunk.
// smem rows: 128B, XOR-swizzled. Stage = A 16KB + B 32KB = 48KB; x3 = 144KB.
// =====================================================================
#define STG_B   49152
#define GEMM_SMEM_BYTES (3 * STG_B)   // 147456
#define NCHUNK  (CDIM / 64)           // 8

__device__ __forceinline__ uint32_t swz(int row, int colByte) {
    return (uint32_t)(row * 128 + (colByte ^ ((row & 7) << 4)));
}

__device__ __forceinline__ void gemm_prefetch(uint32_t smem,
                                              const __half* __restrict__ A,
                                              const __half* __restrict__ B,
                                              int stg, int c) {
    const int tid = threadIdx.x;
    const uint32_t sbase = smem + stg * STG_B;
#pragma unroll
    for (int i = 0; i < 4; i++) {                 // A: 128x64 = 1024 slots
        int idx = tid + i * 256;
        int row = idx >> 3, c8 = idx & 7;
        CP16(sbase + swz(row, c8 * 16), A + (size_t)row * CDIM + c * 64 + c8 * 8);
    }
#pragma unroll
    for (int i = 0; i < 8; i++) {                 // B: 256x64 = 2048 slots
        int idx = tid + i * 256;
        int row = idx >> 3, c8 = idx & 7;
        CP16(sbase + 16384 + swz(row, c8 * 16), B + (size_t)row * CDIM + c * 64 + c8 * 8);
    }
    CP_COMMIT();
}

__device__ __forceinline__ void gemm_mainloop(const __half* __restrict__ A,
                                              const __half* __restrict__ B,
                                              uint32_t smem, float acc[4][8][4]) {
    const int tid  = threadIdx.x;
    const int lane = tid & 31;
    const int wid  = tid >> 5;
    const int wm   = wid >> 2;      // 0..1
    const int wn   = wid & 3;       // 0..3
    const uint32_t mask = (uint32_t)((lane & 7) << 4);
    const uint32_t c0   = (uint32_t)((lane >> 4) * 16);
    const uint32_t aOff = (uint32_t)(wm * 64 + (lane & 15)) * 128;
    const uint32_t bOff = (uint32_t)(wn * 64 + (lane & 15)) * 128;

#pragma unroll
    for (int mf = 0; mf < 4; mf++)
#pragma unroll
        for (int nf = 0; nf < 8; nf++)
#pragma unroll
            for (int r = 0; r < 4; r++) acc[mf][nf][r] = 0.f;

    gemm_prefetch(smem, A, B, 0, 0);
    gemm_prefetch(smem, A, B, 1, 1);

    for (int c = 0; c < NCHUNK; c++) {
        CP_WAIT1();
        __syncthreads();
        if (c + 2 < NCHUNK) gemm_prefetch(smem, A, B, (c + 2) % 3, c + 2);
        else                CP_COMMIT();

        const uint32_t sa = smem + (c % 3) * STG_B;
        const uint32_t sb = sa + 16384;
#pragma unroll
        for (int ks = 0; ks < 4; ks++) {
            const uint32_t col = (c0 + ks * 32);
            uint32_t a[4][4], b[4][4];
#pragma unroll
            for (int mf = 0; mf < 4; mf++)
                LDSM4(a[mf][0], a[mf][1], a[mf][2], a[mf][3],
                      sa + aOff + mf * 2048 + (col ^ mask));
#pragma unroll
            for (int nf = 0; nf < 4; nf++)
                LDSM4(b[nf][0], b[nf][1], b[nf][2], b[nf][3],
                      sb + bOff + nf * 2048 + (col ^ mask));
            // b[nf]: {rows0-7@k0, rows8-15@k0, rows0-7@k8, rows8-15@k8}
#pragma unroll
            for (int mf = 0; mf < 4; mf++)
#pragma unroll
                for (int nf = 0; nf < 4; nf++) {
                    MMA_F16P(acc[mf][2 * nf],     a[mf], b[nf][0], b[nf][2]);
                    MMA_F16P(acc[mf][2 * nf + 1], a[mf], b[nf][1], b[nf][3]);
                }
        }
    }
    CP_WAIT0();
}

// qkv: grid (6, 512); bx = wsel*2 + ntile. Writes fp16 (Q scaled by 0.125).
__global__ __launch_bounds__(256)
void qkv_mma() {
    extern __shared__ char smc[];
    uint32_t smem = smem_u32(smc);
    const int wsel  = blockIdx.x >> 1;
    const int ntile = blockIdx.x & 1;
    const int m0    = blockIdx.y * 128;

    const __half* A = g_x16 + (size_t)m0 * CDIM;
    const __half* B = g_w16 + (size_t)wsel * CDIM * CDIM + (size_t)(ntile * 256) * CDIM;

    float acc[4][8][4];
    gemm_mainloop(A, B, smem, acc);

    __half* Out = (wsel == 0) ? g_q16 : (wsel == 1) ? g_k16 : g_v16;
    const float mul = (wsel == 0) ? 0.125f : 1.0f;

    const int tid = threadIdx.x, wid = tid >> 5, lane = tid & 31;
    const int wm = wid >> 2, wn = wid & 3;
    const int g8 = lane >> 2, tg = lane & 3;
#pragma unroll
    for (int mf = 0; mf < 4; mf++) {
        const int r0 = m0 + wm * 64 + mf * 16 + g8;
#pragma unroll
        for (int nf = 0; nf < 8; nf++) {
            const int col = ntile * 256 + wn * 64 + nf * 8 + 2 * tg;
            *(uint32_t*)(Out + (size_t)r0 * CDIM + col) =
                pkh(acc[mf][nf][0] * mul, acc[mf][nf][1] * mul);
            *(uint32_t*)(Out + (size_t)(r0 + 8) * CDIM + col) =
                pkh(acc[mf][nf][2] * mul, acc[mf][nf][3] * mul);
        }
    }
}

// proj: grid (2, 512). A = g_ao, bias + window-merge scatter to fp32 y.
__global__ __launch_bounds__(256)
void proj_mma(const float* __restrict__ bo, float* __restrict__ y) {
    extern __shared__ char smc[];
    uint32_t smem = smem_u32(smc);
    const int nsel = blockIdx.x;
    const int m0   = blockIdx.y * 128;

    const __half* A = g_ao + (size_t)m0 * CDIM;
    const __half* B = g_w16 + (size_t)3 * CDIM * CDIM + (size_t)(nsel * 256) * CDIM;

    float acc[4][8][4];
    gemm_mainloop(A, B, smem, acc);

    const int tid = threadIdx.x, wid = tid >> 5, lane = tid & 31;
    const int wm = wid >> 2, wn = wid & 3;
    const int g8 = lane >> 2, tg = lane & 3;
#pragma unroll
    for (int mf = 0; mf < 4; mf++) {
        const int r0 = m0 + wm * 64 + mf * 16 + g8;
        const int n0 = win_to_src(r0);
        const int n1 = win_to_src(r0 + 8);
#pragma unroll
        for (int nf = 0; nf < 8; nf++) {
            const int col = nsel * 256 + wn * 64 + nf * 8 + 2 * tg;
            const float b0 = bo[col], b1 = bo[col + 1];
            *(float2*)(y + (size_t)n0 * CDIM + col) =
                make_float2(acc[mf][nf][0] + b0, acc[mf][nf][1] + b1);
            *(float2*)(y + (size_t)n1 * CDIM + col) =
                make_float2(acc[mf][nf][2] + b0, acc[mf][nf][3] + b1);
        }
    }
}

// =====================================================================
// attention (round-6 core, cp.async staging): warp-owns-rows, register
// softmax, P stays in registers for PV. grid 4096, 256 threads.
// =====================================================================
#define ASTRIDE 144
#define QS_OFF  0
#define KS_OFF  (128 * ASTRIDE)
#define VS_OFF  (2 * 128 * ASTRIDE)
#define ATTN_SMEM_BYTES (3 * 128 * ASTRIDE)   // 55296

__global__ __launch_bounds__(256, 2)
void attn_mma() {
    extern __shared__ char smc[];
    uint32_t smem = smem_u32(smc);
    const int tid  = threadIdx.x;
    const int wid  = tid >> 5;
    const int lane = tid & 31;
    const int win = blockIdx.x >> 3;
    const int h   = blockIdx.x & 7;

    const size_t base = (size_t)(win * LWIN) * CDIM + h * HDIM;
#pragma unroll
    for (int i = 0; i < 4; i++) {
        int idx = tid + i * 256;
        int row = idx >> 3, c8 = idx & 7;
        size_t go = base + (size_t)row * CDIM + c8 * 8;
        uint32_t so = (uint32_t)(row * ASTRIDE + c8 * 16);
        CP16(smem + QS_OFF + so, g_q16 + go);
        CP16(smem + KS_OFF + so, g_k16 + go);
        CP16(smem + VS_OFF + so, g_v16 + go);
    }
    CP_COMMIT();
    CP_WAIT0();
    __syncthreads();

    float s[16][4];
#pragma unroll
    for (int nf = 0; nf < 16; nf++)
#pragma unroll
        for (int r = 0; r < 4; r++) s[nf][r] = 0.f;

    const uint32_t aLane = smem + QS_OFF
        + (uint32_t)(wid * 16 + (lane & 15)) * ASTRIDE + (lane >> 4) * 16;
    const uint32_t bBase = smem + KS_OFF
        + (uint32_t)((lane & 7) + ((lane >> 4) & 1) * 8) * ASTRIDE
        + ((lane >> 3) & 1) * 16;

#pragma unroll
    for (int ks = 0; ks < 4; ks++) {
        uint32_t a[4];
        LDSM4(a[0], a[1], a[2], a[3], aLane + ks * 32);
#pragma unroll
        for (int nfp = 0; nfp < 8; nfp++) {
            uint32_t b[4];
            LDSM4(b[0], b[1], b[2], b[3], bBase + nfp * (16 * ASTRIDE) + ks * 32);
            MMA_F16P(s[2 * nfp],     a, b[0], b[1]);
            MMA_F16P(s[2 * nfp + 1], a, b[2], b[3]);
        }
    }

    float mx0 = -1e30f, mx1 = -1e30f;
#pragma unroll
    for (int nf = 0; nf < 16; nf++) {
        mx0 = fmaxf(mx0, fmaxf(s[nf][0], s[nf][1]));
        mx1 = fmaxf(mx1, fmaxf(s[nf][2], s[nf][3]));
    }
    mx0 = fmaxf(mx0, __shfl_xor_sync(0xffffffff, mx0, 1));
    mx0 = fmaxf(mx0, __shfl_xor_sync(0xffffffff, mx0, 2));
    mx1 = fmaxf(mx1, __shfl_xor_sync(0xffffffff, mx1, 1));
    mx1 = fmaxf(mx1, __shfl_xor_sync(0xffffffff, mx1, 2));

    float s0 = 0.f, s1 = 0.f;
#pragma unroll
    for (int nf = 0; nf < 16; nf++) {
        s[nf][0] = __expf(s[nf][0] - mx0);
        s[nf][1] = __expf(s[nf][1] - mx0);
        s[nf][2] = __expf(s[nf][2] - mx1);
        s[nf][3] = __expf(s[nf][3] - mx1);
        s0 += s[nf][0] + s[nf][1];
        s1 += s[nf][2] + s[nf][3];
    }
    s0 += __shfl_xor_sync(0xffffffff, s0, 1);
    s0 += __shfl_xor_sync(0xffffffff, s0, 2);
    s1 += __shfl_xor_sync(0xffffffff, s1, 1);
    s1 += __shfl_xor_sync(0xffffffff, s1, 2);
    const float inv0 = 1.f / s0, inv1 = 1.f / s1;

    uint32_t aP[8][4];
#pragma unroll
    for (int j = 0; j < 8; j++) {
        aP[j][0] = pkh(s[2 * j][0]     * inv0, s[2 * j][1]     * inv0);
        aP[j][1] = pkh(s[2 * j][2]     * inv1, s[2 * j][3]     * inv1);
        aP[j][2] = pkh(s[2 * j + 1][0] * inv0, s[2 * j + 1][1] * inv0);
        aP[j][3] = pkh(s[2 * j + 1][2] * inv1, s[2 * j + 1][3] * inv1);
    }

    float o[8][4];
#pragma unroll
    for (int nf = 0; nf < 8; nf++)
#pragma unroll
        for (int r = 0; r < 4; r++) o[nf][r] = 0.f;

    const uint32_t vBase = smem + VS_OFF
        + (uint32_t)((lane & 7) + ((lane >> 3) & 1) * 8) * ASTRIDE
        + ((lane >> 4) & 1) * 16;

#pragma unroll
    for (int j = 0; j < 8; j++) {
#pragma unroll
        for (int nfp = 0; nfp < 4; nfp++) {
            uint32_t b[4];
            LDSM4T(b[0], b[1], b[2], b[3], vBase + j * (16 * ASTRIDE) + nfp * 32);
            MMA_F16P(o[2 * nfp],     aP[j], b[0], b[1]);
            MMA_F16P(o[2 * nfp + 1], aP[j], b[2], b[3]);
        }
    }

    const int g = lane >> 2, tg = lane & 3;
    const int m0 = win * LWIN + wid * 16;
#pragma unroll
    for (int nf = 0; nf < 8; nf++) {
        const int col = h * HDIM + nf * 8 + 2 * tg;
        *(uint32_t*)(g_ao + (size_t)(m0 + g) * CDIM + col)     = pkh(o[nf][0], o[nf][1]);
        *(uint32_t*)(g_ao + (size_t)(m0 + g + 8) * CDIM + col) = pkh(o[nf][2], o[nf][3]);
    }
}

// =====================================================================
// launcher
// =====================================================================
extern "C" void kernel_launch(void* const* d_in, const int* in_sizes, int n_in,
                              void* d_out, int out_size)
{
    (void)in_sizes; (void)n_in; (void)out_size;
    const float* x  = (const float*)d_in[0];
    const float* Wq = (const float*)d_in[1];
    const float* Wk = (const float*)d_in[2];
    const float* Wv = (const float*)d_in[3];
    const float* Wo = (const float*)d_in[4];
    const float* bo = (const float*)d_in[5];
    float* y = (float*)d_out;

    cudaFuncSetAttribute(qkv_mma,  cudaFuncAttributeMaxDynamicSharedMemorySize, GEMM_SMEM_BYTES);
    cudaFuncSetAttribute(proj_mma, cudaFuncAttributeMaxDynamicSharedMemorySize, GEMM_SMEM_BYTES);
    cudaFuncSetAttribute(attn_mma, cudaFuncAttributeMaxDynamicSharedMemorySize, ATTN_SMEM_BYTES);

    convert_w<<<1024, 256>>>(Wq, Wk, Wv, Wo);
    convert_x<<<32768, 256>>>(x);
    qkv_mma<<<dim3(6, 512), 256, GEMM_SMEM_BYTES>>>();
    attn_mma<<<NWIN * NHEAD, 256, ATTN_SMEM_BYTES>>>();
    proj_mma<<<dim3(2, 512), 256, GEMM_SMEM_BYTES>>>(bo, y);
}

// round 10
// speedup vs baseline: 1.1152x; 1.1152x over previous
#include <cuda_runtime.h>
#include <cuda_fp16.h>
#include <cstdint>
#include <math.h>

// ---------------- problem constants ----------------
#define NTOK   65536
#define CDIM   512
#define NWIN   512
#define LWIN   128
#define NHEAD  8
#define HDIM   64

// ---------------- scratch ----------------
__device__ __half g_x16[(size_t)NTOK * CDIM];   // windowed x, fp16
__device__ __half g_q16[(size_t)NTOK * CDIM];   // Q pre-scaled by 0.125
__device__ __half g_k16[(size_t)NTOK * CDIM];
__device__ __half g_v16[(size_t)NTOK * CDIM];
__device__ __half g_ao[(size_t)NTOK * CDIM];    // attention output (windowed rows)
__device__ __half g_w16[(size_t)4 * CDIM * CDIM];

// windowed row m -> natural token index n
__device__ __forceinline__ int win_to_src(int m) {
    int w = m >> 7, l = m & 127;
    int w1 = w & 7, h1 = (w >> 3) & 7, f1 = w >> 6;
    int iw = l & 7, ih = (l >> 3) & 7, t  = l >> 6;
    return ((f1 * 2 + t) << 12) + ((h1 * 8 + ih) << 6) + (w1 * 8 + iw);
}

// ---------------- PTX helpers ----------------
__device__ __forceinline__ uint32_t smem_u32(const void* p) {
    uint32_t a;
    asm("{ .reg .u64 t; cvta.to.shared.u64 t, %1; cvt.u32.u64 %0, t; }" : "=r"(a) : "l"(p));
    return a;
}
#define CP16(dst, src) \
    asm volatile("cp.async.cg.shared.global [%0], [%1], 16;" :: "r"(dst), "l"(src))
#define CP_COMMIT() asm volatile("cp.async.commit_group;" ::: "memory")
#define CP_WAIT1()  asm volatile("cp.async.wait_group 1;" ::: "memory")
#define CP_WAIT0()  asm volatile("cp.async.wait_group 0;" ::: "memory")

#define LDSM4(r0, r1, r2, r3, a) \
    asm volatile("ldmatrix.sync.aligned.m8n8.x4.shared.b16 {%0,%1,%2,%3}, [%4];" \
                 : "=r"(r0), "=r"(r1), "=r"(r2), "=r"(r3) : "r"(a))
#define LDSM2(r0, r1, a) \
    asm volatile("ldmatrix.sync.aligned.m8n8.x2.shared.b16 {%0,%1}, [%2];" \
                 : "=r"(r0), "=r"(r1) : "r"(a))
#define LDSM4T(r0, r1, r2, r3, a) \
    asm volatile("ldmatrix.sync.aligned.m8n8.x4.trans.shared.b16 {%0,%1,%2,%3}, [%4];" \
                 : "=r"(r0), "=r"(r1), "=r"(r2), "=r"(r3) : "r"(a))

// c += a * {b0,b1}
#define MMA_F16P(c, a, b0, b1) \
    asm volatile("mma.sync.aligned.m16n8k16.row.col.f32.f16.f16.f32 " \
                 "{%0,%1,%2,%3}, {%4,%5,%6,%7}, {%8,%9}, {%0,%1,%2,%3};" \
                 : "+f"((c)[0]), "+f"((c)[1]), "+f"((c)[2]), "+f"((c)[3]) \
                 : "r"((a)[0]), "r"((a)[1]), "r"((a)[2]), "r"((a)[3]), \
                   "r"(b0), "r"(b1))
#define MMA_F16(c, a, b) MMA_F16P(c, a, (b)[0], (b)[1])

__device__ __forceinline__ uint32_t pkh(float a, float b) {
    __half2 h = __float22half2_rn(make_float2(a, b));
    return *reinterpret_cast<uint32_t*>(&h);
}

// =====================================================================
// conversion: one kernel. blocks 0..32767 -> x ; 32768..33791 -> weights
// =====================================================================
__global__ void convert_all(const float* __restrict__ x,
                            const float* __restrict__ Wq, const float* __restrict__ Wk,
                            const float* __restrict__ Wv, const float* __restrict__ Wo) {
    int b = blockIdx.x;
    if (b < 32768) {
        int idx = b * 256 + threadIdx.x;
        int m = idx >> 7, q = idx & 127;
        int n = win_to_src(m);
        float4 v = *(const float4*)(x + (size_t)n * CDIM + q * 4);
        __half* dst = g_x16 + (size_t)m * CDIM + q * 4;
        *(__half2*)(dst)     = __float22half2_rn(make_float2(v.x, v.y));
        *(__half2*)(dst + 2) = __float22half2_rn(make_float2(v.z, v.w));
    } else {
        int wb = b - 32768;
        int sel = wb >> 8;
        int rem = (wb & 255) * 256 + threadIdx.x;
        const float* W = (sel == 0) ? Wq : (sel == 1) ? Wk : (sel == 2) ? Wv : Wo;
        float4 v = *(const float4*)(W + (size_t)rem * 4);
        __half* dst = g_w16 + (size_t)sel * CDIM * CDIM + (size_t)rem * 4;
        *(__half2*)(dst)     = __float22half2_rn(make_float2(v.x, v.y));
        *(__half2*)(dst + 2) = __float22half2_rn(make_float2(v.z, v.w));
    }
}

// =====================================================================
// GEMM (round-6 engine): C[128,128] = A[128,512] @ B[128,512]^T.
// 256 threads = 8 warps (2m x 4n), warp tile 64x32. BK=64, 3-stage ring.
// smem row stride 144B; one barrier per chunk.
// =====================================================================
#define GSTRIDE   144
#define GTILE_B   (128 * GSTRIDE)         // 18432
#define GSTAGE_B  (2 * GTILE_B)           // 36864
#define GEMM_SMEM_BYTES (3 * GSTAGE_B)    // 110592
#define NCHUNK    (CDIM / 64)             // 8

__device__ __forceinline__ void gemm_prefetch(const __half* __restrict__ A,
                                              const __half* __restrict__ B,
                                              uint32_t sa, uint32_t sb, int c) {
    const int tid = threadIdx.x;
#pragma unroll
    for (int i = 0; i < 4; i++) {
        int idx = tid + i * 256;
        int row = idx >> 3, c8 = idx & 7;
        uint32_t so = row * GSTRIDE + c8 * 16;
        CP16(sa + so, A + (size_t)row * CDIM + c * 64 + c8 * 8);
        CP16(sb + so, B + (size_t)row * CDIM + c * 64 + c8 * 8);
    }
    CP_COMMIT();
}

__device__ __forceinline__ void gemm_mainloop(const __half* __restrict__ A,
                                              const __half* __restrict__ B,
                                              uint32_t smem, float acc[4][4][4]) {
    const int tid  = threadIdx.x;
    const int wid  = tid >> 5;
    const int lane = tid & 31;
    const int wm   = wid >> 2;
    const int wn   = wid & 3;

    const uint32_t aLane = (uint32_t)(wm * 64 + (lane & 15)) * GSTRIDE + (lane >> 4) * 16;
    const uint32_t bLane = (uint32_t)(wn * 32 + (lane & 7)) * GSTRIDE
                         + ((lane >> 3) & 1) * 16;

#pragma unroll
    for (int mf = 0; mf < 4; mf++)
#pragma unroll
        for (int nf = 0; nf < 4; nf++)
#pragma unroll
            for (int r = 0; r < 4; r++) acc[mf][nf][r] = 0.f;

    gemm_prefetch(A, B, smem, smem + GTILE_B, 0);
    gemm_prefetch(A, B, smem + GSTAGE_B, smem + GSTAGE_B + GTILE_B, 1);

    for (int c = 0; c < NCHUNK; c++) {
        CP_WAIT1();
        __syncthreads();
        if (c + 2 < NCHUNK) {
            const uint32_t pb = smem + ((c + 2) % 3) * GSTAGE_B;
            gemm_prefetch(A, B, pb, pb + GTILE_B, c + 2);
        } else {
            CP_COMMIT();
        }
        const uint32_t sa = smem + (c % 3) * GSTAGE_B;
        const uint32_t sb = sa + GTILE_B;
#pragma unroll
        for (int ks = 0; ks < 4; ks++) {
            uint32_t a[4][4], b[4][2];
#pragma unroll
            for (int mf = 0; mf < 4; mf++)
                LDSM4(a[mf][0], a[mf][1], a[mf][2], a[mf][3],
                      sa + aLane + mf * (16 * GSTRIDE) + ks * 32);
#pragma unroll
            for (int nf = 0; nf < 4; nf++)
                LDSM2(b[nf][0], b[nf][1],
                      sb + bLane + nf * (8 * GSTRIDE) + ks * 32);
#pragma unroll
            for (int mf = 0; mf < 4; mf++)
#pragma unroll
                for (int nf = 0; nf < 4; nf++)
                    MMA_F16(acc[mf][nf], a[mf], b[nf]);
        }
    }
    CP_WAIT0();
}

// qkv: grid (12, 512); bx = wsel*4 + ntile. Writes fp16 (Q scaled by 0.125).
__global__ __launch_bounds__(256, 2)
void qkv_mma() {
    extern __shared__ char smc[];
    uint32_t smem = smem_u32(smc);
    const int wsel  = blockIdx.x >> 2;
    const int ntile = blockIdx.x & 3;
    const int m0    = blockIdx.y * 128;

    const __half* A = g_x16 + (size_t)m0 * CDIM;
    const __half* B = g_w16 + (size_t)wsel * CDIM * CDIM + (size_t)(ntile * 128) * CDIM;

    float acc[4][4][4];
    gemm_mainloop(A, B, smem, acc);

    __half* Out = (wsel == 0) ? g_q16 : (wsel == 1) ? g_k16 : g_v16;
    const float mul = (wsel == 0) ? 0.125f : 1.0f;

    const int tid = threadIdx.x, wid = tid >> 5, lane = tid & 31;
    const int wm = wid >> 2, wn = wid & 3;
    const int g = lane >> 2, tg = lane & 3;
#pragma unroll
    for (int mf = 0; mf < 4; mf++) {
        const int r0 = m0 + wm * 64 + mf * 16 + g;
#pragma unroll
        for (int nf = 0; nf < 4; nf++) {
            const int col = ntile * 128 + wn * 32 + nf * 8 + 2 * tg;
            *(uint32_t*)(Out + (size_t)r0 * CDIM + col) =
                pkh(acc[mf][nf][0] * mul, acc[mf][nf][1] * mul);
            *(uint32_t*)(Out + (size_t)(r0 + 8) * CDIM + col) =
                pkh(acc[mf][nf][2] * mul, acc[mf][nf][3] * mul);
        }
    }
}

// proj: grid (4, 512). A = g_ao, bias + window-merge scatter to fp32 y.
__global__ __launch_bounds__(256, 2)
void proj_mma(const float* __restrict__ bo, float* __restrict__ y) {
    extern __shared__ char smc[];
    uint32_t smem = smem_u32(smc);
    const int ntile = blockIdx.x;
    const int m0    = blockIdx.y * 128;

    const __half* A = g_ao + (size_t)m0 * CDIM;
    const __half* B = g_w16 + (size_t)3 * CDIM * CDIM + (size_t)(ntile * 128) * CDIM;

    float acc[4][4][4];
    gemm_mainloop(A, B, smem, acc);

    const int tid = threadIdx.x, wid = tid >> 5, lane = tid & 31;
    const int wm = wid >> 2, wn = wid & 3;
    const int g = lane >> 2, tg = lane & 3;
#pragma unroll
    for (int mf = 0; mf < 4; mf++) {
        const int r0 = m0 + wm * 64 + mf * 16 + g;
        const int n0 = win_to_src(r0);
        const int n1 = win_to_src(r0 + 8);
#pragma unroll
        for (int nf = 0; nf < 4; nf++) {
            const int col = ntile * 128 + wn * 32 + nf * 8 + 2 * tg;
            const float b0 = bo[col], b1 = bo[col + 1];
            *(float2*)(y + (size_t)n0 * CDIM + col) =
                make_float2(acc[mf][nf][0] + b0, acc[mf][nf][1] + b1);
            *(float2*)(y + (size_t)n1 * CDIM + col) =
                make_float2(acc[mf][nf][2] + b0, acc[mf][nf][3] + b1);
        }
    }
}

// =====================================================================
// attention (round-9): warp-owns-rows, register softmax, cp.async staging.
// grid 4096, 256 threads, 2 CTAs/SM.
// =====================================================================
#define ASTRIDE 144
#define QS_OFF  0
#define KS_OFF  (128 * ASTRIDE)
#define VS_OFF  (2 * 128 * ASTRIDE)
#define ATTN_SMEM_BYTES (3 * 128 * ASTRIDE)   // 55296

__global__ __launch_bounds__(256, 2)
void attn_mma() {
    extern __shared__ char smc[];
    uint32_t smem = smem_u32(smc);
    const int tid  = threadIdx.x;
    const int wid  = tid >> 5;
    const int lane = tid & 31;
    const int win = blockIdx.x >> 3;
    const int h   = blockIdx.x & 7;

    const size_t base = (size_t)(win * LWIN) * CDIM + h * HDIM;
#pragma unroll
    for (int i = 0; i < 4; i++) {
        int idx = tid + i * 256;
        int row = idx >> 3, c8 = idx & 7;
        size_t go = base + (size_t)row * CDIM + c8 * 8;
        uint32_t so = (uint32_t)(row * ASTRIDE + c8 * 16);
        CP16(smem + QS_OFF + so, g_q16 + go);
        CP16(smem + KS_OFF + so, g_k16 + go);
        CP16(smem + VS_OFF + so, g_v16 + go);
    }
    CP_COMMIT();
    CP_WAIT0();
    __syncthreads();

    float s[16][4];
#pragma unroll
    for (int nf = 0; nf < 16; nf++)
#pragma unroll
        for (int r = 0; r < 4; r++) s[nf][r] = 0.f;

    const uint32_t aLane = smem + QS_OFF
        + (uint32_t)(wid * 16 + (lane & 15)) * ASTRIDE + (lane >> 4) * 16;
    const uint32_t bBase = smem + KS_OFF
        + (uint32_t)((lane & 7) + ((lane >> 4) & 1) * 8) * ASTRIDE
        + ((lane >> 3) & 1) * 16;

#pragma unroll
    for (int ks = 0; ks < 4; ks++) {
        uint32_t a[4];
        LDSM4(a[0], a[1], a[2], a[3], aLane + ks * 32);
#pragma unroll
        for (int nfp = 0; nfp < 8; nfp++) {
            uint32_t b[4];
            LDSM4(b[0], b[1], b[2], b[3], bBase + nfp * (16 * ASTRIDE) + ks * 32);
            MMA_F16P(s[2 * nfp],     a, b[0], b[1]);
            MMA_F16P(s[2 * nfp + 1], a, b[2], b[3]);
        }
    }

    float mx0 = -1e30f, mx1 = -1e30f;
#pragma unroll
    for (int nf = 0; nf < 16; nf++) {
        mx0 = fmaxf(mx0, fmaxf(s[nf][0], s[nf][1]));
        mx1 = fmaxf(mx1, fmaxf(s[nf][2], s[nf][3]));
    }
    mx0 = fmaxf(mx0, __shfl_xor_sync(0xffffffff, mx0, 1));
    mx0 = fmaxf(mx0, __shfl_xor_sync(0xffffffff, mx0, 2));
    mx1 = fmaxf(mx1, __shfl_xor_sync(0xffffffff, mx1, 1));
    mx1 = fmaxf(mx1, __shfl_xor_sync(0xffffffff, mx1, 2));

    float s0 = 0.f, s1 = 0.f;
#pragma unroll
    for (int nf = 0; nf < 16; nf++) {
        s[nf][0] = __expf(s[nf][0] - mx0);
        s[nf][1] = __expf(s[nf][1] - mx0);
        s[nf][2] = __expf(s[nf][2] - mx1);
        s[nf][3] = __expf(s[nf][3] - mx1);
        s0 += s[nf][0] + s[nf][1];
        s1 += s[nf][2] + s[nf][3];
    }
    s0 += __shfl_xor_sync(0xffffffff, s0, 1);
    s0 += __shfl_xor_sync(0xffffffff, s0, 2);
    s1 += __shfl_xor_sync(0xffffffff, s1, 1);
    s1 += __shfl_xor_sync(0xffffffff, s1, 2);
    const float inv0 = 1.f / s0, inv1 = 1.f / s1;

    uint32_t aP[8][4];
#pragma unroll
    for (int j = 0; j < 8; j++) {
        aP[j][0] = pkh(s[2 * j][0]     * inv0, s[2 * j][1]     * inv0);
        aP[j][1] = pkh(s[2 * j][2]     * inv1, s[2 * j][3]     * inv1);
        aP[j][2] = pkh(s[2 * j + 1][0] * inv0, s[2 * j + 1][1] * inv0);
        aP[j][3] = pkh(s[2 * j + 1][2] * inv1, s[2 * j + 1][3] * inv1);
    }

    float o[8][4];
#pragma unroll
    for (int nf = 0; nf < 8; nf++)
#pragma unroll
        for (int r = 0; r < 4; r++) o[nf][r] = 0.f;

    const uint32_t vBase = smem + VS_OFF
        + (uint32_t)((lane & 7) + ((lane >> 3) & 1) * 8) * ASTRIDE
        + ((lane >> 4) & 1) * 16;

#pragma unroll
    for (int j = 0; j < 8; j++) {
#pragma unroll
        for (int nfp = 0; nfp < 4; nfp++) {
            uint32_t b[4];
            LDSM4T(b[0], b[1], b[2], b[3], vBase + j * (16 * ASTRIDE) + nfp * 32);
            MMA_F16P(o[2 * nfp],     aP[j], b[0], b[1]);
            MMA_F16P(o[2 * nfp + 1], aP[j], b[2], b[3]);
        }
    }

    const int g = lane >> 2, tg = lane & 3;
    const int m0 = win * LWIN + wid * 16;
#pragma unroll
    for (int nf = 0; nf < 8; nf++) {
        const int col = h * HDIM + nf * 8 + 2 * tg;
        *(uint32_t*)(g_ao + (size_t)(m0 + g) * CDIM + col)     = pkh(o[nf][0], o[nf][1]);
        *(uint32_t*)(g_ao + (size_t)(m0 + g + 8) * CDIM + col) = pkh(o[nf][2], o[nf][3]);
    }
}

// =====================================================================
// launcher
// =====================================================================
extern "C" void kernel_launch(void* const* d_in, const int* in_sizes, int n_in,
                              void* d_out, int out_size)
{
    (void)in_sizes; (void)n_in; (void)out_size;
    const float* x  = (const float*)d_in[0];
    const float* Wq = (const float*)d_in[1];
    const float* Wk = (const float*)d_in[2];
    const float* Wv = (const float*)d_in[3];
    const float* Wo = (const float*)d_in[4];
    const float* bo = (const float*)d_in[5];
    float* y = (float*)d_out;

    cudaFuncSetAttribute(qkv_mma,  cudaFuncAttributeMaxDynamicSharedMemorySize, GEMM_SMEM_BYTES);
    cudaFuncSetAttribute(proj_mma, cudaFuncAttributeMaxDynamicSharedMemorySize, GEMM_SMEM_BYTES);
    cudaFuncSetAttribute(attn_mma, cudaFuncAttributeMaxDynamicSharedMemorySize, ATTN_SMEM_BYTES);

    convert_all<<<33792, 256>>>(x, Wq, Wk, Wv, Wo);
    qkv_mma<<<dim3(12, 512), 256, GEMM_SMEM_BYTES>>>();
    attn_mma<<<NWIN * NHEAD, 256, ATTN_SMEM_BYTES>>>();
    proj_mma<<<dim3(4, 512), 256, GEMM_SMEM_BYTES>>>(bo, y);
}

// round 12
// speedup vs baseline: 1.1204x; 1.0047x over previous
#include <cuda_runtime.h>
#include <cuda_fp16.h>
#include <cstdint>
#include <math.h>

// ---------------- problem constants ----------------
#define NTOK   65536
#define CDIM   512
#define NWIN   512
#define LWIN   128
#define NHEAD  8
#define HDIM   64

// ---------------- scratch ----------------
__device__ __half g_x16[(size_t)NTOK * CDIM];   // windowed x, fp16
__device__ __half g_q16[(size_t)NTOK * CDIM];   // Q pre-scaled by 0.125
__device__ __half g_k16[(size_t)NTOK * CDIM];
__device__ __half g_v16[(size_t)NTOK * CDIM];
__device__ __half g_ao[(size_t)NTOK * CDIM];    // attention output (windowed rows)
__device__ __half g_w16[(size_t)4 * CDIM * CDIM];

// windowed row m -> natural token index n
__device__ __forceinline__ int win_to_src(int m) {
    int w = m >> 7, l = m & 127;
    int w1 = w & 7, h1 = (w >> 3) & 7, f1 = w >> 6;
    int iw = l & 7, ih = (l >> 3) & 7, t  = l >> 6;
    return ((f1 * 2 + t) << 12) + ((h1 * 8 + ih) << 6) + (w1 * 8 + iw);
}

// ---------------- PTX helpers ----------------
__device__ __forceinline__ uint32_t smem_u32(const void* p) {
    uint32_t a;
    asm("{ .reg .u64 t; cvta.to.shared.u64 t, %1; cvt.u32.u64 %0, t; }" : "=r"(a) : "l"(p));
    return a;
}
#define CP16(dst, src) \
    asm volatile("cp.async.cg.shared.global [%0], [%1], 16;" :: "r"(dst), "l"(src))
#define CP_COMMIT() asm volatile("cp.async.commit_group;" ::: "memory")
#define CP_WAIT1()  asm volatile("cp.async.wait_group 1;" ::: "memory")
#define CP_WAIT0()  asm volatile("cp.async.wait_group 0;" ::: "memory")

#define LDSM4(r0, r1, r2, r3, a) \
    asm volatile("ldmatrix.sync.aligned.m8n8.x4.shared.b16 {%0,%1,%2,%3}, [%4];" \
                 : "=r"(r0), "=r"(r1), "=r"(r2), "=r"(r3) : "r"(a))
#define LDSM2(r0, r1, a) \
    asm volatile("ldmatrix.sync.aligned.m8n8.x2.shared.b16 {%0,%1}, [%2];" \
                 : "=r"(r0), "=r"(r1) : "r"(a))
#define LDSM4T(r0, r1, r2, r3, a) \
    asm volatile("ldmatrix.sync.aligned.m8n8.x4.trans.shared.b16 {%0,%1,%2,%3}, [%4];" \
                 : "=r"(r0), "=r"(r1), "=r"(r2), "=r"(r3) : "r"(a))

// c += a * {b0,b1}
#define MMA_F16P(c, a, b0, b1) \
    asm volatile("mma.sync.aligned.m16n8k16.row.col.f32.f16.f16.f32 " \
                 "{%0,%1,%2,%3}, {%4,%5,%6,%7}, {%8,%9}, {%0,%1,%2,%3};" \
                 : "+f"((c)[0]), "+f"((c)[1]), "+f"((c)[2]), "+f"((c)[3]) \
                 : "r"((a)[0]), "r"((a)[1]), "r"((a)[2]), "r"((a)[3]), \
                   "r"(b0), "r"(b1))
#define MMA_F16(c, a, b) MMA_F16P(c, a, (b)[0], (b)[1])

__device__ __forceinline__ uint32_t pkh(float a, float b) {
    __half2 h = __float22half2_rn(make_float2(a, b));
    return *reinterpret_cast<uint32_t*>(&h);
}

// =====================================================================
// conversion: one kernel. blocks 0..32767 -> x ; 32768..33791 -> weights
// =====================================================================
__global__ void convert_all(const float* __restrict__ x,
                            const float* __restrict__ Wq, const float* __restrict__ Wk,
                            const float* __restrict__ Wv, const float* __restrict__ Wo) {
    int b = blockIdx.x;
    if (b < 32768) {
        int idx = b * 256 + threadIdx.x;
        int m = idx >> 7, q = idx & 127;
        int n = win_to_src(m);
        float4 v = *(const float4*)(x + (size_t)n * CDIM + q * 4);
        __half* dst = g_x16 + (size_t)m * CDIM + q * 4;
        *(__half2*)(dst)     = __float22half2_rn(make_float2(v.x, v.y));
        *(__half2*)(dst + 2) = __float22half2_rn(make_float2(v.z, v.w));
    } else {
        int wb = b - 32768;
        int sel = wb >> 8;
        int rem = (wb & 255) * 256 + threadIdx.x;
        const float* W = (sel == 0) ? Wq : (sel == 1) ? Wk : (sel == 2) ? Wv : Wo;
        float4 v = *(const float4*)(W + (size_t)rem * 4);
        __half* dst = g_w16 + (size_t)sel * CDIM * CDIM + (size_t)rem * 4;
        *(__half2*)(dst)     = __float22half2_rn(make_float2(v.x, v.y));
        *(__half2*)(dst + 2) = __float22half2_rn(make_float2(v.z, v.w));
    }
}

// =====================================================================
// GEMM (round-6 engine): C[128,128] = A[128,512] @ B[128,512]^T.
// 256 threads = 8 warps (2m x 4n), warp tile 64x32. BK=64, 3-stage ring.
// =====================================================================
#define GSTRIDE   144
#define GTILE_B   (128 * GSTRIDE)         // 18432
#define GSTAGE_B  (2 * GTILE_B)           // 36864
#define GEMM_SMEM_BYTES (3 * GSTAGE_B)    // 110592
#define NCHUNK    (CDIM / 64)             // 8

__device__ __forceinline__ void gemm_prefetch(const __half* __restrict__ A,
                                              const __half* __restrict__ B,
                                              uint32_t sa, uint32_t sb, int c) {
    const int tid = threadIdx.x;
#pragma unroll
    for (int i = 0; i < 4; i++) {
        int idx = tid + i * 256;
        int row = idx >> 3, c8 = idx & 7;
        uint32_t so = row * GSTRIDE + c8 * 16;
        CP16(sa + so, A + (size_t)row * CDIM + c * 64 + c8 * 8);
        CP16(sb + so, B + (size_t)row * CDIM + c * 64 + c8 * 8);
    }
    CP_COMMIT();
}

__device__ __forceinline__ void gemm_mainloop(const __half* __restrict__ A,
                                              const __half* __restrict__ B,
                                              uint32_t smem, float acc[4][4][4]) {
    const int tid  = threadIdx.x;
    const int wid  = tid >> 5;
    const int lane = tid & 31;
    const int wm   = wid >> 2;
    const int wn   = wid & 3;

    const uint32_t aLane = (uint32_t)(wm * 64 + (lane & 15)) * GSTRIDE + (lane >> 4) * 16;
    const uint32_t bLane = (uint32_t)(wn * 32 + (lane & 7)) * GSTRIDE
                         + ((lane >> 3) & 1) * 16;

#pragma unroll
    for (int mf = 0; mf < 4; mf++)
#pragma unroll
        for (int nf = 0; nf < 4; nf++)
#pragma unroll
            for (int r = 0; r < 4; r++) acc[mf][nf][r] = 0.f;

    gemm_prefetch(A, B, smem, smem + GTILE_B, 0);
    gemm_prefetch(A, B, smem + GSTAGE_B, smem + GSTAGE_B + GTILE_B, 1);

    for (int c = 0; c < NCHUNK; c++) {
        CP_WAIT1();
        __syncthreads();
        if (c + 2 < NCHUNK) {
            const uint32_t pb = smem + ((c + 2) % 3) * GSTAGE_B;
            gemm_prefetch(A, B, pb, pb + GTILE_B, c + 2);
        } else {
            CP_COMMIT();
        }
        const uint32_t sa = smem + (c % 3) * GSTAGE_B;
        const uint32_t sb = sa + GTILE_B;
#pragma unroll
        for (int ks = 0; ks < 4; ks++) {
            uint32_t a[4][4], b[4][2];
#pragma unroll
            for (int mf = 0; mf < 4; mf++)
                LDSM4(a[mf][0], a[mf][1], a[mf][2], a[mf][3],
                      sa + aLane + mf * (16 * GSTRIDE) + ks * 32);
#pragma unroll
            for (int nf = 0; nf < 4; nf++)
                LDSM2(b[nf][0], b[nf][1],
                      sb + bLane + nf * (8 * GSTRIDE) + ks * 32);
#pragma unroll
            for (int mf = 0; mf < 4; mf++)
#pragma unroll
                for (int nf = 0; nf < 4; nf++)
                    MMA_F16(acc[mf][nf], a[mf], b[nf]);
        }
    }
    CP_WAIT0();
}

// qkv: grid (12, 512); bx = wsel*4 + ntile. Smem-staged coalesced epilogue.
#define QSTG 272   // fp16 staging row stride (bytes), 16B-aligned, 68w % 32 = 4
__global__ __launch_bounds__(256, 2)
void qkv_mma() {
    extern __shared__ char smc[];
    uint32_t smem = smem_u32(smc);
    const int wsel  = blockIdx.x >> 2;
    const int ntile = blockIdx.x & 3;
    const int m0    = blockIdx.y * 128;

    const __half* A = g_x16 + (size_t)m0 * CDIM;
    const __half* B = g_w16 + (size_t)wsel * CDIM * CDIM + (size_t)(ntile * 128) * CDIM;

    float acc[4][4][4];
    gemm_mainloop(A, B, smem, acc);

    __half* Out = (wsel == 0) ? g_q16 : (wsel == 1) ? g_k16 : g_v16;
    const float mul = (wsel == 0) ? 0.125f : 1.0f;

    const int tid = threadIdx.x, wid = tid >> 5, lane = tid & 31;
    const int wm = wid >> 2, wn = wid & 3;
    const int g = lane >> 2, tg = lane & 3;

    __syncthreads();   // ring no longer read by any warp; reuse as staging
#pragma unroll
    for (int mf = 0; mf < 4; mf++) {
        const int r0 = wm * 64 + mf * 16 + g;
#pragma unroll
        for (int nf = 0; nf < 4; nf++) {
            const int col = wn * 32 + nf * 8 + 2 * tg;
            *(uint32_t*)(smc + r0 * QSTG + col * 2) =
                pkh(acc[mf][nf][0] * mul, acc[mf][nf][1] * mul);
            *(uint32_t*)(smc + (r0 + 8) * QSTG + col * 2) =
                pkh(acc[mf][nf][2] * mul, acc[mf][nf][3] * mul);
        }
    }
    __syncthreads();
#pragma unroll
    for (int i = 0; i < 8; i++) {          // 128 rows x 16 uint4
        int idx = tid + i * 256;
        int row = idx >> 4, c8 = idx & 15;
        uint4 v = *(const uint4*)(smc + row * QSTG + c8 * 16);
        *(uint4*)(Out + (size_t)(m0 + row) * CDIM + ntile * 128 + c8 * 8) = v;
    }
}

// proj: grid (4, 512). Smem-staged coalesced scatter (row-level gather only).
#define PSTG 528   // fp32 staging row stride (bytes), 16B-aligned, 132w % 32 = 4
__global__ __launch_bounds__(256, 2)
void proj_mma(const float* __restrict__ bo, float* __restrict__ y) {
    extern __shared__ char smc[];
    uint32_t smem = smem_u32(smc);
    const int ntile = blockIdx.x;
    const int m0    = blockIdx.y * 128;

    const __half* A = g_ao + (size_t)m0 * CDIM;
    const __half* B = g_w16 + (size_t)3 * CDIM * CDIM + (size_t)(ntile * 128) * CDIM;

    float acc[4][4][4];
    gemm_mainloop(A, B, smem, acc);

    const int tid = threadIdx.x, wid = tid >> 5, lane = tid & 31;
    const int wm = wid >> 2, wn = wid & 3;
    const int g = lane >> 2, tg = lane & 3;

    __syncthreads();   // reuse ring as fp32 staging (128 x 528B = 67.5KB)
#pragma unroll
    for (int mf = 0; mf < 4; mf++) {
        const int r0 = wm * 64 + mf * 16 + g;
#pragma unroll
        for (int nf = 0; nf < 4; nf++) {
            const int col = wn * 32 + nf * 8 + 2 * tg;
            const float b0 = bo[ntile * 128 + col], b1 = bo[ntile * 128 + col + 1];
            float* p0 = (float*)(smc + r0 * PSTG + col * 4);
            float* p1 = (float*)(smc + (r0 + 8) * PSTG + col * 4);
            p0[0] = acc[mf][nf][0] + b0; p0[1] = acc[mf][nf][1] + b1;
            p1[0] = acc[mf][nf][2] + b0; p1[1] = acc[mf][nf][3] + b1;
        }
    }
    __syncthreads();
#pragma unroll
    for (int i = 0; i < 16; i++) {         // 128 rows x 32 float4
        int idx = tid + i * 256;
        int row = idx >> 5, c4 = idx & 31;
        float4 v = *(const float4*)(smc + row * PSTG + c4 * 16);
        const int n = win_to_src(m0 + row);
        *(float4*)(y + (size_t)n * CDIM + ntile * 128 + c4 * 4) = v;
    }
}

// =====================================================================
// attention: warp-owns-rows, register softmax, SPLIT cp.async staging
// (Q+K group, then V group; V hidden behind S+softmax). grid 4096.
// =====================================================================
#define ASTRIDE 144
#define QS_OFF  0
#define KS_OFF  (128 * ASTRIDE)
#define VS_OFF  (2 * 128 * ASTRIDE)
#define ATTN_SMEM_BYTES (3 * 128 * ASTRIDE)   // 55296

__global__ __launch_bounds__(256, 2)
void attn_mma() {
    extern __shared__ char smc[];
    uint32_t smem = smem_u32(smc);
    const int tid  = threadIdx.x;
    const int wid  = tid >> 5;
    const int lane = tid & 31;
    const int win = blockIdx.x >> 3;
    const int h   = blockIdx.x & 7;

    const size_t base = (size_t)(win * LWIN) * CDIM + h * HDIM;
#pragma unroll
    for (int i = 0; i < 4; i++) {          // group 0: Q + K
        int idx = tid + i * 256;
        int row = idx >> 3, c8 = idx & 7;
        size_t go = base + (size_t)row * CDIM + c8 * 8;
        uint32_t so = (uint32_t)(row * ASTRIDE + c8 * 16);
        CP16(smem + QS_OFF + so, g_q16 + go);
        CP16(smem + KS_OFF + so, g_k16 + go);
    }
    CP_COMMIT();
#pragma unroll
    for (int i = 0; i < 4; i++) {          // group 1: V
        int idx = tid + i * 256;
        int row = idx >> 3, c8 = idx & 7;
        CP16(smem + VS_OFF + (uint32_t)(row * ASTRIDE + c8 * 16),
             g_v16 + base + (size_t)row * CDIM + c8 * 8);
    }
    CP_COMMIT();
    CP_WAIT1();                             // Q,K ready; V in flight
    __syncthreads();

    float s[16][4];
#pragma unroll
    for (int nf = 0; nf < 16; nf++)
#pragma unroll
        for (int r = 0; r < 4; r++) s[nf][r] = 0.f;

    const uint32_t aLane = smem + QS_OFF
        + (uint32_t)(wid * 16 + (lane & 15)) * ASTRIDE + (lane >> 4) * 16;
    const uint32_t bBase = smem + KS_OFF
        + (uint32_t)((lane & 7) + ((lane >> 4) & 1) * 8) * ASTRIDE
        + ((lane >> 3) & 1) * 16;

#pragma unroll
    for (int ks = 0; ks < 4; ks++) {
        uint32_t a[4];
        LDSM4(a[0], a[1], a[2], a[3], aLane + ks * 32);
#pragma unroll
        for (int nfp = 0; nfp < 8; nfp++) {
            uint32_t b[4];
            LDSM4(b[0], b[1], b[2], b[3], bBase + nfp * (16 * ASTRIDE) + ks * 32);
            MMA_F16P(s[2 * nfp],     a, b[0], b[1]);
            MMA_F16P(s[2 * nfp + 1], a, b[2], b[3]);
        }
    }

    float mx0 = -1e30f, mx1 = -1e30f;
#pragma unroll
    for (int nf = 0; nf < 16; nf++) {
        mx0 = fmaxf(mx0, fmaxf(s[nf][0], s[nf][1]));
        mx1 = fmaxf(mx1, fmaxf(s[nf][2], s[nf][3]));
    }
    mx0 = fmaxf(mx0, __shfl_xor_sync(0xffffffff, mx0, 1));
    mx0 = fmaxf(mx0, __shfl_xor_sync(0xffffffff, mx0, 2));
    mx1 = fmaxf(mx1, __shfl_xor_sync(0xffffffff, mx1, 1));
    mx1 = fmaxf(mx1, __shfl_xor_sync(0xffffffff, mx1, 2));

    float s0 = 0.f, s1 = 0.f;
#pragma unroll
    for (int nf = 0; nf < 16; nf++) {
        s[nf][0] = __expf(s[nf][0] - mx0);
        s[nf][1] = __expf(s[nf][1] - mx0);
        s[nf][2] = __expf(s[nf][2] - mx1);
        s[nf][3] = __expf(s[nf][3] - mx1);
        s0 += s[nf][0] + s[nf][1];
        s1 += s[nf][2] + s[nf][3];
    }
    s0 += __shfl_xor_sync(0xffffffff, s0, 1);
    s0 += __shfl_xor_sync(0xffffffff, s0, 2);
    s1 += __shfl_xor_sync(0xffffffff, s1, 1);
    s1 += __shfl_xor_sync(0xffffffff, s1, 2);
    const float inv0 = 1.f / s0, inv1 = 1.f / s1;

    uint32_t aP[8][4];
#pragma unroll
    for (int j = 0; j < 8; j++) {
        aP[j][0] = pkh(s[2 * j][0]     * inv0, s[2 * j][1]     * inv0);
        aP[j][1] = pkh(s[2 * j][2]     * inv1, s[2 * j][3]     * inv1);
        aP[j][2] = pkh(s[2 * j + 1][0] * inv0, s[2 * j + 1][1] * inv0);
        aP[j][3] = pkh(s[2 * j + 1][2] * inv1, s[2 * j + 1][3] * inv1);
    }

    CP_WAIT0();                             // V complete
    __syncthreads();

    float o[8][4];
#pragma unroll
    for (int nf = 0; nf < 8; nf++)
#pragma unroll
        for (int r = 0; r < 4; r++) o[nf][r] = 0.f;

    const uint32_t vBase = smem + VS_OFF
        + (uint32_t)((lane & 7) + ((lane >> 3) & 1) * 8) * ASTRIDE
        + ((lane >> 4) & 1) * 16;

#pragma unroll
    for (int j = 0; j < 8; j++) {
#pragma unroll
        for (int nfp = 0; nfp < 4; nfp++) {
            uint32_t b[4];
            LDSM4T(b[0], b[1], b[2], b[3], vBase + j * (16 * ASTRIDE) + nfp * 32);
            MMA_F16P(o[2 * nfp],     aP[j], b[0], b[1]);
            MMA_F16P(o[2 * nfp + 1], aP[j], b[2], b[3]);
        }
    }

    const int g = lane >> 2, tg = lane & 3;
    const int m0 = win * LWIN + wid * 16;
#pragma unroll
    for (int nf = 0; nf < 8; nf++) {
        const int col = h * HDIM + nf * 8 + 2 * tg;
        *(uint32_t*)(g_ao + (size_t)(m0 + g) * CDIM + col)     = pkh(o[nf][0], o[nf][1]);
        *(uint32_t*)(g_ao + (size_t)(m0 + g + 8) * CDIM + col) = pkh(o[nf][2], o[nf][3]);
    }
}

// =====================================================================
// launcher
// =====================================================================
extern "C" void kernel_launch(void* const* d_in, const int* in_sizes, int n_in,
                              void* d_out, int out_size)
{
    (void)in_sizes; (void)n_in; (void)out_size;
    const float* x  = (const float*)d_in[0];
    const float* Wq = (const float*)d_in[1];
    const float* Wk = (const float*)d_in[2];
    const float* Wv = (const float*)d_in[3];
    const float* Wo = (const float*)d_in[4];
    const float* bo = (const float*)d_in[5];
    float* y = (float*)d_out;

    cudaFuncSetAttribute(qkv_mma,  cudaFuncAttributeMaxDynamicSharedMemorySize, GEMM_SMEM_BYTES);
    cudaFuncSetAttribute(proj_mma, cudaFuncAttributeMaxDynamicSharedMemorySize, GEMM_SMEM_BYTES);
    cudaFuncSetAttribute(attn_mma, cudaFuncAttributeMaxDynamicSharedMemorySize, ATTN_SMEM_BYTES);

    convert_all<<<33792, 256>>>(x, Wq, Wk, Wv, Wo);
    qkv_mma<<<dim3(12, 512), 256, GEMM_SMEM_BYTES>>>();
    attn_mma<<<NWIN * NHEAD, 256, ATTN_SMEM_BYTES>>>();
    proj_mma<<<dim3(4, 512), 256, GEMM_SMEM_BYTES>>>(bo, y);
}

// round 13
// speedup vs baseline: 1.1424x; 1.0196x over previous
#include <cuda_runtime.h>
#include <cuda_fp16.h>
#include <cstdint>
#include <math.h>

// ---------------- problem constants ----------------
#define NTOK   65536
#define CDIM   512
#define NWIN   512
#define LWIN   128
#define NHEAD  8
#define HDIM   64

// ---------------- scratch ----------------
__device__ __half g_x16[(size_t)NTOK * CDIM];   // windowed x, fp16
__device__ __half g_q16[(size_t)NTOK * CDIM];   // Q pre-scaled by 0.125
__device__ __half g_k16[(size_t)NTOK * CDIM];
__device__ __half g_v16[(size_t)NTOK * CDIM];
__device__ __half g_ao[(size_t)NTOK * CDIM];    // attention output (windowed rows)
__device__ __half g_w16[(size_t)4 * CDIM * CDIM];

// windowed row m -> natural token index n
__device__ __forceinline__ int win_to_src(int m) {
    int w = m >> 7, l = m & 127;
    int w1 = w & 7, h1 = (w >> 3) & 7, f1 = w >> 6;
    int iw = l & 7, ih = (l >> 3) & 7, t  = l >> 6;
    return ((f1 * 2 + t) << 12) + ((h1 * 8 + ih) << 6) + (w1 * 8 + iw);
}

// ---------------- PTX helpers ----------------
__device__ __forceinline__ uint32_t smem_u32(const void* p) {
    uint32_t a;
    asm("{ .reg .u64 t; cvta.to.shared.u64 t, %1; cvt.u32.u64 %0, t; }" : "=r"(a) : "l"(p));
    return a;
}
#define CP16(dst, src) \
    asm volatile("cp.async.cg.shared.global [%0], [%1], 16;" :: "r"(dst), "l"(src))
#define CP_COMMIT() asm volatile("cp.async.commit_group;" ::: "memory")
#define CP_WAIT1()  asm volatile("cp.async.wait_group 1;" ::: "memory")
#define CP_WAIT0()  asm volatile("cp.async.wait_group 0;" ::: "memory")

#define LDSM4(r0, r1, r2, r3, a) \
    asm volatile("ldmatrix.sync.aligned.m8n8.x4.shared.b16 {%0,%1,%2,%3}, [%4];" \
                 : "=r"(r0), "=r"(r1), "=r"(r2), "=r"(r3) : "r"(a))
#define LDSM2(r0, r1, a) \
    asm volatile("ldmatrix.sync.aligned.m8n8.x2.shared.b16 {%0,%1}, [%2];" \
                 : "=r"(r0), "=r"(r1) : "r"(a))
#define LDSM4T(r0, r1, r2, r3, a) \
    asm volatile("ldmatrix.sync.aligned.m8n8.x4.trans.shared.b16 {%0,%1,%2,%3}, [%4];" \
                 : "=r"(r0), "=r"(r1), "=r"(r2), "=r"(r3) : "r"(a))

// c += a * {b0,b1}
#define MMA_F16P(c, a, b0, b1) \
    asm volatile("mma.sync.aligned.m16n8k16.row.col.f32.f16.f16.f32 " \
                 "{%0,%1,%2,%3}, {%4,%5,%6,%7}, {%8,%9}, {%0,%1,%2,%3};" \
                 : "+f"((c)[0]), "+f"((c)[1]), "+f"((c)[2]), "+f"((c)[3]) \
                 : "r"((a)[0]), "r"((a)[1]), "r"((a)[2]), "r"((a)[3]), \
                   "r"(b0), "r"(b1))
#define MMA_F16(c, a, b) MMA_F16P(c, a, (b)[0], (b)[1])

__device__ __forceinline__ uint32_t pkh(float a, float b) {
    __half2 h = __float22half2_rn(make_float2(a, b));
    return *reinterpret_cast<uint32_t*>(&h);
}

// =====================================================================
// conversion: one kernel. blocks 0..32767 -> x ; 32768..33791 -> weights
// =====================================================================
__global__ void convert_all(const float* __restrict__ x,
                            const float* __restrict__ Wq, const float* __restrict__ Wk,
                            const float* __restrict__ Wv, const float* __restrict__ Wo) {
    int b = blockIdx.x;
    if (b < 32768) {
        int idx = b * 256 + threadIdx.x;
        int m = idx >> 7, q = idx & 127;
        int n = win_to_src(m);
        float4 v = *(const float4*)(x + (size_t)n * CDIM + q * 4);
        __half* dst = g_x16 + (size_t)m * CDIM + q * 4;
        *(__half2*)(dst)     = __float22half2_rn(make_float2(v.x, v.y));
        *(__half2*)(dst + 2) = __float22half2_rn(make_float2(v.z, v.w));
    } else {
        int wb = b - 32768;
        int sel = wb >> 8;
        int rem = (wb & 255) * 256 + threadIdx.x;
        const float* W = (sel == 0) ? Wq : (sel == 1) ? Wk : (sel == 2) ? Wv : Wo;
        float4 v = *(const float4*)(W + (size_t)rem * 4);
        __half* dst = g_w16 + (size_t)sel * CDIM * CDIM + (size_t)rem * 4;
        *(__half2*)(dst)     = __float22half2_rn(make_float2(v.x, v.y));
        *(__half2*)(dst + 2) = __float22half2_rn(make_float2(v.z, v.w));
    }
}

// =====================================================================
// GEMM (round-6 engine): C[128,128] = A[128,512] @ B[128,512]^T.
// 256 threads = 8 warps (2m x 4n), warp tile 64x32. BK=64, 3-stage ring.
// =====================================================================
#define GSTRIDE   144
#define GTILE_B   (128 * GSTRIDE)         // 18432
#define GSTAGE_B  (2 * GTILE_B)           // 36864
#define GEMM_SMEM_BYTES (3 * GSTAGE_B)    // 110592
#define NCHUNK    (CDIM / 64)             // 8

__device__ __forceinline__ void gemm_prefetch(const __half* __restrict__ A,
                                              const __half* __restrict__ B,
                                              uint32_t sa, uint32_t sb, int c) {
    const int tid = threadIdx.x;
#pragma unroll
    for (int i = 0; i < 4; i++) {
        int idx = tid + i * 256;
        int row = idx >> 3, c8 = idx & 7;
        uint32_t so = row * GSTRIDE + c8 * 16;
        CP16(sa + so, A + (size_t)row * CDIM + c * 64 + c8 * 8);
        CP16(sb + so, B + (size_t)row * CDIM + c * 64 + c8 * 8);
    }
    CP_COMMIT();
}

__device__ __forceinline__ void gemm_mainloop(const __half* __restrict__ A,
                                              const __half* __restrict__ B,
                                              uint32_t smem, float acc[4][4][4]) {
    const int tid  = threadIdx.x;
    const int wid  = tid >> 5;
    const int lane = tid & 31;
    const int wm   = wid >> 2;
    const int wn   = wid & 3;

    const uint32_t aLane = (uint32_t)(wm * 64 + (lane & 15)) * GSTRIDE + (lane >> 4) * 16;
    const uint32_t bLane = (uint32_t)(wn * 32 + (lane & 7)) * GSTRIDE
                         + ((lane >> 3) & 1) * 16;

#pragma unroll
    for (int mf = 0; mf < 4; mf++)
#pragma unroll
        for (int nf = 0; nf < 4; nf++)
#pragma unroll
            for (int r = 0; r < 4; r++) acc[mf][nf][r] = 0.f;

    gemm_prefetch(A, B, smem, smem + GTILE_B, 0);
    gemm_prefetch(A, B, smem + GSTAGE_B, smem + GSTAGE_B + GTILE_B, 1);

    for (int c = 0; c < NCHUNK; c++) {
        CP_WAIT1();
        __syncthreads();
        if (c + 2 < NCHUNK) {
            const uint32_t pb = smem + ((c + 2) % 3) * GSTAGE_B;
            gemm_prefetch(A, B, pb, pb + GTILE_B, c + 2);
        } else {
            CP_COMMIT();
        }
        const uint32_t sa = smem + (c % 3) * GSTAGE_B;
        const uint32_t sb = sa + GTILE_B;
#pragma unroll
        for (int ks = 0; ks < 4; ks++) {
            uint32_t a[4][4], b[4][2];
#pragma unroll
            for (int mf = 0; mf < 4; mf++)
                LDSM4(a[mf][0], a[mf][1], a[mf][2], a[mf][3],
                      sa + aLane + mf * (16 * GSTRIDE) + ks * 32);
#pragma unroll
            for (int nf = 0; nf < 4; nf++)
                LDSM2(b[nf][0], b[nf][1],
                      sb + bLane + nf * (8 * GSTRIDE) + ks * 32);
#pragma unroll
            for (int mf = 0; mf < 4; mf++)
#pragma unroll
                for (int nf = 0; nf < 4; nf++)
                    MMA_F16(acc[mf][nf], a[mf], b[nf]);
        }
    }
    CP_WAIT0();
}

// qkv: grid (12, 512); bx = wsel*4 + ntile. Smem-staged coalesced epilogue.
#define QSTG 272   // fp16 staging row stride (bytes), 16B-aligned, 68w % 32 = 4
__global__ __launch_bounds__(256, 2)
void qkv_mma() {
    extern __shared__ char smc[];
    uint32_t smem = smem_u32(smc);
    const int wsel  = blockIdx.x >> 2;
    const int ntile = blockIdx.x & 3;
    const int m0    = blockIdx.y * 128;

    const __half* A = g_x16 + (size_t)m0 * CDIM;
    const __half* B = g_w16 + (size_t)wsel * CDIM * CDIM + (size_t)(ntile * 128) * CDIM;

    float acc[4][4][4];
    gemm_mainloop(A, B, smem, acc);

    __half* Out = (wsel == 0) ? g_q16 : (wsel == 1) ? g_k16 : g_v16;
    const float mul = (wsel == 0) ? 0.125f : 1.0f;

    const int tid = threadIdx.x, wid = tid >> 5, lane = tid & 31;
    const int wm = wid >> 2, wn = wid & 3;
    const int g = lane >> 2, tg = lane & 3;

    __syncthreads();   // ring no longer read by any warp; reuse as staging
#pragma unroll
    for (int mf = 0; mf < 4; mf++) {
        const int r0 = wm * 64 + mf * 16 + g;
#pragma unroll
        for (int nf = 0; nf < 4; nf++) {
            const int col = wn * 32 + nf * 8 + 2 * tg;
            *(uint32_t*)(smc + r0 * QSTG + col * 2) =
                pkh(acc[mf][nf][0] * mul, acc[mf][nf][1] * mul);
            *(uint32_t*)(smc + (r0 + 8) * QSTG + col * 2) =
                pkh(acc[mf][nf][2] * mul, acc[mf][nf][3] * mul);
        }
    }
    __syncthreads();
#pragma unroll
    for (int i = 0; i < 8; i++) {          // 128 rows x 16 uint4
        int idx = tid + i * 256;
        int row = idx >> 4, c8 = idx & 15;
        uint4 v = *(const uint4*)(smc + row * QSTG + c8 * 16);
        *(uint4*)(Out + (size_t)(m0 + row) * CDIM + ntile * 128 + c8 * 8) = v;
    }
}

// proj: grid (4, 512). Direct-store epilogue (round-10; measured fastest).
__global__ __launch_bounds__(256, 2)
void proj_mma(const float* __restrict__ bo, float* __restrict__ y) {
    extern __shared__ char smc[];
    uint32_t smem = smem_u32(smc);
    const int ntile = blockIdx.x;
    const int m0    = blockIdx.y * 128;

    const __half* A = g_ao + (size_t)m0 * CDIM;
    const __half* B = g_w16 + (size_t)3 * CDIM * CDIM + (size_t)(ntile * 128) * CDIM;

    float acc[4][4][4];
    gemm_mainloop(A, B, smem, acc);

    const int tid = threadIdx.x, wid = tid >> 5, lane = tid & 31;
    const int wm = wid >> 2, wn = wid & 3;
    const int g = lane >> 2, tg = lane & 3;
#pragma unroll
    for (int mf = 0; mf < 4; mf++) {
        const int r0 = m0 + wm * 64 + mf * 16 + g;
        const int n0 = win_to_src(r0);
        const int n1 = win_to_src(r0 + 8);
#pragma unroll
        for (int nf = 0; nf < 4; nf++) {
            const int col = ntile * 128 + wn * 32 + nf * 8 + 2 * tg;
            const float b0 = bo[col], b1 = bo[col + 1];
            *(float2*)(y + (size_t)n0 * CDIM + col) =
                make_float2(acc[mf][nf][0] + b0, acc[mf][nf][1] + b1);
            *(float2*)(y + (size_t)n1 * CDIM + col) =
                make_float2(acc[mf][nf][2] + b0, acc[mf][nf][3] + b1);
        }
    }
}

// =====================================================================
// attention: warp-owns-rows, register softmax, SPLIT cp.async staging
// (Q+K group, then V group; V hidden behind S+softmax). grid 4096.
// =====================================================================
#define ASTRIDE 144
#define QS_OFF  0
#define KS_OFF  (128 * ASTRIDE)
#define VS_OFF  (2 * 128 * ASTRIDE)
#define ATTN_SMEM_BYTES (3 * 128 * ASTRIDE)   // 55296

__global__ __launch_bounds__(256, 2)
void attn_mma() {
    extern __shared__ char smc[];
    uint32_t smem = smem_u32(smc);
    const int tid  = threadIdx.x;
    const int wid  = tid >> 5;
    const int lane = tid & 31;
    const int win = blockIdx.x >> 3;
    const int h   = blockIdx.x & 7;

    const size_t base = (size_t)(win * LWIN) * CDIM + h * HDIM;
#pragma unroll
    for (int i = 0; i < 4; i++) {          // group 0: Q + K
        int idx = tid + i * 256;
        int row = idx >> 3, c8 = idx & 7;
        size_t go = base + (size_t)row * CDIM + c8 * 8;
        uint32_t so = (uint32_t)(row * ASTRIDE + c8 * 16);
        CP16(smem + QS_OFF + so, g_q16 + go);
        CP16(smem + KS_OFF + so, g_k16 + go);
    }
    CP_COMMIT();
#pragma unroll
    for (int i = 0; i < 4; i++) {          // group 1: V
        int idx = tid + i * 256;
        int row = idx >> 3, c8 = idx & 7;
        CP16(smem + VS_OFF + (uint32_t)(row * ASTRIDE + c8 * 16),
             g_v16 + base + (size_t)row * CDIM + c8 * 8);
    }
    CP_COMMIT();
    CP_WAIT1();                             // Q,K ready; V in flight
    __syncthreads();

    float s[16][4];
#pragma unroll
    for (int nf = 0; nf < 16; nf++)
#pragma unroll
        for (int r = 0; r < 4; r++) s[nf][r] = 0.f;

    const uint32_t aLane = smem + QS_OFF
        + (uint32_t)(wid * 16 + (lane & 15)) * ASTRIDE + (lane >> 4) * 16;
    const uint32_t bBase = smem + KS_OFF
        + (uint32_t)((lane & 7) + ((lane >> 4) & 1) * 8) * ASTRIDE
        + ((lane >> 3) & 1) * 16;

#pragma unroll
    for (int ks = 0; ks < 4; ks++) {
        uint32_t a[4];
        LDSM4(a[0], a[1], a[2], a[3], aLane + ks * 32);
#pragma unroll
        for (int nfp = 0; nfp < 8; nfp++) {
            uint32_t b[4];
            LDSM4(b[0], b[1], b[2], b[3], bBase + nfp * (16 * ASTRIDE) + ks * 32);
            MMA_F16P(s[2 * nfp],     a, b[0], b[1]);
            MMA_F16P(s[2 * nfp + 1], a, b[2], b[3]);
        }
    }

    float mx0 = -1e30f, mx1 = -1e30f;
#pragma unroll
    for (int nf = 0; nf < 16; nf++) {
        mx0 = fmaxf(mx0, fmaxf(s[nf][0], s[nf][1]));
        mx1 = fmaxf(mx1, fmaxf(s[nf][2], s[nf][3]));
    }
    mx0 = fmaxf(mx0, __shfl_xor_sync(0xffffffff, mx0, 1));
    mx0 = fmaxf(mx0, __shfl_xor_sync(0xffffffff, mx0, 2));
    mx1 = fmaxf(mx1, __shfl_xor_sync(0xffffffff, mx1, 1));
    mx1 = fmaxf(mx1, __shfl_xor_sync(0xffffffff, mx1, 2));

    float s0 = 0.f, s1 = 0.f;
#pragma unroll
    for (int nf = 0; nf < 16; nf++) {
        s[nf][0] = __expf(s[nf][0] - mx0);
        s[nf][1] = __expf(s[nf][1] - mx0);
        s[nf][2] = __expf(s[nf][2] - mx1);
        s[nf][3] = __expf(s[nf][3] - mx1);
        s0 += s[nf][0] + s[nf][1];
        s1 += s[nf][2] + s[nf][3];
    }
    s0 += __shfl_xor_sync(0xffffffff, s0, 1);
    s0 += __shfl_xor_sync(0xffffffff, s0, 2);
    s1 += __shfl_xor_sync(0xffffffff, s1, 1);
    s1 += __shfl_xor_sync(0xffffffff, s1, 2);
    const float inv0 = 1.f / s0, inv1 = 1.f / s1;

    uint32_t aP[8][4];
#pragma unroll
    for (int j = 0; j < 8; j++) {
        aP[j][0] = pkh(s[2 * j][0]     * inv0, s[2 * j][1]     * inv0);
        aP[j][1] = pkh(s[2 * j][2]     * inv1, s[2 * j][3]     * inv1);
        aP[j][2] = pkh(s[2 * j + 1][0] * inv0, s[2 * j + 1][1] * inv0);
        aP[j][3] = pkh(s[2 * j + 1][2] * inv1, s[2 * j + 1][3] * inv1);
    }

    CP_WAIT0();                             // V complete
    __syncthreads();

    float o[8][4];
#pragma unroll
    for (int nf = 0; nf < 8; nf++)
#pragma unroll
        for (int r = 0; r < 4; r++) o[nf][r] = 0.f;

    const uint32_t vBase = smem + VS_OFF
        + (uint32_t)((lane & 7) + ((lane >> 3) & 1) * 8) * ASTRIDE
        + ((lane >> 4) & 1) * 16;

#pragma unroll
    for (int j = 0; j < 8; j++) {
#pragma unroll
        for (int nfp = 0; nfp < 4; nfp++) {
            uint32_t b[4];
            LDSM4T(b[0], b[1], b[2], b[3], vBase + j * (16 * ASTRIDE) + nfp * 32);
            MMA_F16P(o[2 * nfp],     aP[j], b[0], b[1]);
            MMA_F16P(o[2 * nfp + 1], aP[j], b[2], b[3]);
        }
    }

    const int g = lane >> 2, tg = lane & 3;
    const int m0 = win * LWIN + wid * 16;
#pragma unroll
    for (int nf = 0; nf < 8; nf++) {
        const int col = h * HDIM + nf * 8 + 2 * tg;
        *(uint32_t*)(g_ao + (size_t)(m0 + g) * CDIM + col)     = pkh(o[nf][0], o[nf][1]);
        *(uint32_t*)(g_ao + (size_t)(m0 + g + 8) * CDIM + col) = pkh(o[nf][2], o[nf][3]);
    }
}

// =====================================================================
// launcher
// =====================================================================
extern "C" void kernel_launch(void* const* d_in, const int* in_sizes, int n_in,
                              void* d_out, int out_size)
{
    (void)in_sizes; (void)n_in; (void)out_size;
    const float* x  = (const float*)d_in[0];
    const float* Wq = (const float*)d_in[1];
    const float* Wk = (const float*)d_in[2];
    const float* Wv = (const float*)d_in[3];
    const float* Wo = (const float*)d_in[4];
    const float* bo = (const float*)d_in[5];
    float* y = (float*)d_out;

    cudaFuncSetAttribute(qkv_mma,  cudaFuncAttributeMaxDynamicSharedMemorySize, GEMM_SMEM_BYTES);
    cudaFuncSetAttribute(proj_mma, cudaFuncAttributeMaxDynamicSharedMemorySize, GEMM_SMEM_BYTES);
    cudaFuncSetAttribute(attn_mma, cudaFuncAttributeMaxDynamicSharedMemorySize, ATTN_SMEM_BYTES);

    convert_all<<<33792, 256>>>(x, Wq, Wk, Wv, Wo);
    qkv_mma<<<dim3(12, 512), 256, GEMM_SMEM_BYTES>>>();
    attn_mma<<<NWIN * NHEAD, 256, ATTN_SMEM_BYTES>>>();
    proj_mma<<<dim3(4, 512), 256, GEMM_SMEM_BYTES>>>(bo, y);
}